// round 7
// baseline (speedup 1.0000x reference)
#include <cuda_runtime.h>
#include <cstdint>

#define BATCH 64
#define NTOK  65536            // 256*256
#define KSEL  16384
#define TOTAL (BATCH * NTOK)
#define CANDCAP 4096           // per-batch candidate capacity (global)
#define WCAP    192            // per-warp candidate capacity (expected 82, 12 sigma)

// ---- device scratch (device globals; no allocations) ----
__device__ uint32_t g_cand[BATCH * CANDCAP];
__device__ uint32_t g_nc[BATCH];     // candidate counts (zero-init; reset by finalize)
__device__ uint32_t g_c2[BATCH];     // counts >= P2     (zero-init; reset by finalize)
__device__ uint32_t g_of[BATCH];     // overflow flags   (zero-init; reset by finalize)
__device__ uint32_t g_T[BATCH];      // threshold bit pattern
__device__ uint32_t g_req[BATCH];    // #(==T) to include
__device__ uint32_t g_eqcnt[BATCH];  // runtime tie counter
__device__ double   g_acc;           // loss accumulator
__device__ unsigned g_done;          // finalize ticket

#define P1F 0.73f
#define P2F 0.77f

// ============================================================================
// Kernel 1: smap sweep (16 MB). Warp-autonomous: per-warp smem candidate
// buffer + register counter (ballot/popc). NO __syncthreads anywhere.
// 256 blocks (4/batch) x 256 thr x 16 uint4 (64 elements) per thread.
// ============================================================================
__global__ __launch_bounds__(256) void gather_kernel(const uint4* __restrict__ sm4) {
    __shared__ uint32_t scand[8 * WCAP];

    const int t    = threadIdx.x;
    const int lane = t & 31;
    const int w    = t >> 5;
    const int b    = blockIdx.x >> 2;              // 4 blocks per batch
    const int base = blockIdx.x * 4096;            // uint4 base for this block

    const uint32_t P1 = __float_as_uint(P1F);
    const uint32_t P2 = __float_as_uint(P2F);
    const uint32_t W  = P2 - P1;

    uint32_t* wbuf = scand + w * WCAP;
    uint32_t cnt2 = 0;     // count of u >= P2 (per thread)
    uint32_t cw   = 0;     // warp candidate count (uniform across warp)

    #pragma unroll
    for (int r = 0; r < 4; r++) {
        uint4 v[4];
        #pragma unroll
        for (int j = 0; j < 4; j++)
            v[j] = sm4[base + r * 1024 + j * 256 + t];
        #pragma unroll
        for (int j = 0; j < 4; j++) {
            #pragma unroll
            for (int c = 0; c < 4; c++) {
                uint32_t u = (c == 0) ? v[j].x : (c == 1) ? v[j].y
                           : (c == 2) ? v[j].z : v[j].w;
                cnt2 += (u >= P2);
                bool isC = (u - P1) < W;           // P1 <= u < P2 (positive floats)
                unsigned m = __ballot_sync(0xFFFFFFFFu, isC);
                if (isC) {
                    uint32_t idx = cw + __popc(m & ((1u << lane) - 1u));
                    if (idx < WCAP) wbuf[idx] = u;
                }
                cw += __popc(m);
            }
        }
    }

    // warp-reduce cnt2
    #pragma unroll
    for (int off = 16; off > 0; off >>= 1)
        cnt2 += __shfl_down_sync(0xFFFFFFFFu, cnt2, off);

    uint32_t n = (cw > WCAP) ? WCAP : cw;
    uint32_t gbase = 0;
    if (lane == 0) {
        atomicAdd(&g_c2[b], cnt2);
        if (cw > WCAP) g_of[b] = 1u;
        gbase = atomicAdd(&g_nc[b], n);
        if (gbase + n > CANDCAP) g_of[b] = 1u;
    }
    gbase = __shfl_sync(0xFFFFFFFFu, gbase, 0);
    __syncwarp();
    for (uint32_t i = lane; i < n; i += 32)
        if (gbase + i < CANDCAP) g_cand[b * CANDCAP + gbase + i] = wbuf[i];
}

// ============================================================================
// Kernel 2: per-batch exact threshold. Normal path: candidates are in
// [P1, P2), so select on 20-bit keys (u - P1) in 2 rounds of 10 bits.
// Miss fallback: 4x8-bit full radix over smap (never taken at this input).
// ============================================================================
__device__ __forceinline__ uint32_t suffix_excl_512(uint32_t v, uint32_t* wsum) {
    const int t = threadIdx.x, lane = t & 31, w = t >> 5;
    uint32_t s = v;
    #pragma unroll
    for (int off = 1; off < 32; off <<= 1) {
        uint32_t o = __shfl_down_sync(0xFFFFFFFFu, s, off);
        if (lane + off < 32) s += o;
    }
    if (lane == 0) wsum[w] = s;
    __syncthreads();
    if (t < 32) {
        uint32_t x  = (t < 16) ? wsum[t] : 0u;
        uint32_t sx = x;
        #pragma unroll
        for (int off = 1; off < 16; off <<= 1) {
            uint32_t o = __shfl_down_sync(0xFFFFFFFFu, sx, off);
            if (t + off < 16) sx += o;
        }
        if (t < 16) wsum[t] = sx - x;
    }
    __syncthreads();
    return wsum[w] + (s - v);
}

__global__ __launch_bounds__(512) void thresh_kernel(const float* __restrict__ smap) {
    __shared__ uint32_t hist[1024];
    __shared__ uint32_t wsum[32];
    __shared__ uint32_t sBin, sK;

    const int b = blockIdx.x;
    const int t = threadIdx.x;
    const uint32_t P1 = __float_as_uint(P1F);

    const uint32_t nc = g_nc[b];
    const uint32_t c2 = g_c2[b];
    const bool miss = (g_of[b] != 0u) || (c2 >= KSEL) || (c2 + nc < KSEL) || (nc > CANDCAP);

    const uint32_t* __restrict__ cand = g_cand + b * CANDCAP;
    const uint32_t* __restrict__ full =
        reinterpret_cast<const uint32_t*>(smap) + (size_t)b * NTOK;

    if (!miss) {
        // ---- 2-round select on 20-bit keys (u - P1) ----
        uint32_t Kcur = (uint32_t)KSEL - c2;
        uint32_t prefixVal = 0;          // selected high bits of the 20-bit key
        #pragma unroll
        for (int r = 0; r < 2; r++) {
            const int shift = (r == 0) ? 10 : 0;
            for (int i = t; i < 1024; i += 512) hist[i] = 0u;
            __syncthreads();
            for (uint32_t i = t; i < nc; i += 512) {
                uint32_t k = cand[i] - P1;                     // < 2^20
                bool match = (r == 0) || ((k >> 10) == prefixVal);
                if (match) atomicAdd(&hist[(k >> shift) & 1023u], 1u);
            }
            __syncthreads();
            const int base = t * 2;
            uint32_t p = hist[base] + hist[base + 1];
            uint32_t sfx = suffix_excl_512(p, wsum);
            for (int j = 1; j >= 0; j--) {
                uint32_t h = hist[base + j];
                uint32_t s_incl = sfx + h;
                if (sfx < Kcur && s_incl >= Kcur) { sBin = (uint32_t)(base + j); sK = Kcur - sfx; }
                sfx = s_incl;
            }
            __syncthreads();
            prefixVal = (prefixVal << 10) | sBin;
            Kcur = sK;
            __syncthreads();
        }
        if (t == 0) { g_T[b] = P1 + prefixVal; g_req[b] = Kcur; }
    } else {
        // ---- fallback: 4x8-bit full radix over all NTOK values ----
        uint32_t Kcur = KSEL;
        uint32_t prefixVal = 0;
        for (int r = 0; r < 4; r++) {
            const int shift = 24 - 8 * r;
            for (int i = t; i < 256; i += 512) hist[i] = 0u;
            __syncthreads();
            for (int i = t; i < NTOK; i += 512) {
                uint32_t u = full[i];
                bool match = (r == 0) || ((u >> (shift + 8)) == prefixVal);
                if (match) atomicAdd(&hist[(u >> shift) & 255u], 1u);
            }
            __syncthreads();
            uint32_t p = (t < 256) ? hist[t] : 0u;
            uint32_t sfx = suffix_excl_512(p, wsum);
            if (t < 256) {
                uint32_t s_incl = sfx + p;
                if (sfx < Kcur && s_incl >= Kcur) { sBin = (uint32_t)t; sK = Kcur - sfx; }
            }
            __syncthreads();
            prefixVal = (prefixVal << 8) | sBin;
            Kcur = sK;
            __syncthreads();
        }
        if (t == 0) { g_T[b] = prefixVal; g_req[b] = Kcur; }
    }
}

// ============================================================================
// Kernel 3: loss sweep (67 MB scores+gumbel DRAM + 16 MB smap, L2-hot).
// term = min(c + max(x,0), 100), x = sel ? -d : d, c = ln(1+e^{-|x|}).
// 2048 blocks x 256 thr x 2 groups; launch_bounds caps regs for occupancy.
// ============================================================================
__global__ __launch_bounds__(256, 6) void loss_kernel(const float4* __restrict__ zs4,
                                                      const uint4*  __restrict__ sm4,
                                                      const float4* __restrict__ gn4,
                                                      float* __restrict__ out,
                                                      unsigned nblocks) {
    __shared__ double wpart[8];
    const int t    = threadIdx.x;
    const int lane = t & 31;
    const int w    = t >> 5;
    const int b    = blockIdx.x >> 5;               // 32 blocks per batch
    const int blockBase = blockIdx.x * 512;
    const uint32_t T = g_T[b];

    float facc = 0.0f;
    #pragma unroll
    for (int j = 0; j < 2; j++) {
        const int g = blockBase + j * 256 + t;
        uint4  u  = sm4[g];
        float4 za = __ldcs(&zs4[2 * g]);
        float4 zb = __ldcs(&zs4[2 * g + 1]);
        float4 ga = __ldcs(&gn4[2 * g]);
        float4 gb = __ldcs(&gn4[2 * g + 1]);

        float d0 = (za.x + ga.x) - (za.y + ga.y);
        float d1 = (za.z + ga.z) - (za.w + ga.w);
        float d2 = (zb.x + gb.x) - (zb.y + gb.y);
        float d3 = (zb.z + gb.z) - (zb.w + gb.w);

        #pragma unroll
        for (int c = 0; c < 4; c++) {
            float    d  = (c == 0) ? d0 : (c == 1) ? d1 : (c == 2) ? d2 : d3;
            uint32_t uu = (c == 0) ? u.x : (c == 1) ? u.y : (c == 2) ? u.z : u.w;
            bool sel;
            if (uu > T)       sel = true;
            else if (uu == T) sel = (atomicAdd(&g_eqcnt[b], 1u) < g_req[b]);  // rare
            else              sel = false;
            float x = sel ? -d : d;
            float cc = __logf(1.0f + __expf(-fabsf(x)));
            facc += fminf(cc + fmaxf(x, 0.0f), 100.0f);
        }
    }

    double acc = (double)facc;
    #pragma unroll
    for (int off = 16; off > 0; off >>= 1)
        acc += __shfl_down_sync(0xFFFFFFFFu, acc, off);
    if (lane == 0) wpart[w] = acc;
    __syncthreads();

    if (t == 0) {
        double bsum = 0.0;
        #pragma unroll
        for (int i = 0; i < 8; i++) bsum += wpart[i];
        atomicAdd(&g_acc, bsum);
        __threadfence();
        unsigned ticket = atomicAdd(&g_done, 1u);
        if (ticket == nblocks - 1) {                 // last block: finalize + reset
            __threadfence();
            out[0] = (float)atomicAdd(&g_acc, 0.0);
            #pragma unroll 4
            for (int i = 0; i < BATCH; i++) {
                g_c2[i] = 0u; g_nc[i] = 0u; g_of[i] = 0u; g_eqcnt[i] = 0u;
            }
            g_acc = 0.0;
            __threadfence();
            g_done = 0u;
        }
    }
}

extern "C" void kernel_launch(void* const* d_in, const int* in_sizes, int n_in,
                              void* d_out, int out_size) {
    const float* scores = (const float*)d_in[0];   // [B, N, 2]
    const float* smap   = (const float*)d_in[1];   // [B, 1, H, W] == [B, N]
    const float* gumb   = (const float*)d_in[2];   // [B, N, 2]
    float* out = (float*)d_out;

    gather_kernel<<<256, 256>>>((const uint4*)smap);
    thresh_kernel<<<BATCH, 512>>>(smap);
    loss_kernel<<<2048, 256>>>((const float4*)scores, (const uint4*)smap,
                               (const float4*)gumb, out, 2048u);
}

// round 8
// speedup vs baseline: 1.0078x; 1.0078x over previous
#include <cuda_runtime.h>
#include <cstdint>

#define BATCH 64
#define NTOK  65536            // 256*256
#define KSEL  16384
#define TOTAL (BATCH * NTOK)
#define CANDCAP 4096           // per-batch candidate capacity (global)
#define WCAP    64             // per-warp candidate capacity (expected ~20.5, 10 sigma)

// ---- device scratch (device globals; no allocations) ----
__device__ uint32_t g_cand[BATCH * CANDCAP];
__device__ uint32_t g_nc[BATCH];     // candidate counts (zero-init; reset by finalize)
__device__ uint32_t g_c2[BATCH];     // counts >= P2     (zero-init; reset by finalize)
__device__ uint32_t g_of[BATCH];     // overflow flags   (zero-init; reset by finalize)
__device__ uint32_t g_T[BATCH];      // threshold bit pattern
__device__ uint32_t g_req[BATCH];    // #(==T) to include
__device__ uint32_t g_eqcnt[BATCH];  // runtime tie counter
__device__ double   g_acc;           // loss accumulator
__device__ unsigned g_done;          // finalize ticket

#define P1F 0.73f
#define P2F 0.77f

// ============================================================================
// Kernel 1: smap sweep (16 MB). Warp-autonomous: per-warp smem candidate
// buffer + ballot/popc counter. NO __syncthreads. 1024 blocks (16/batch)
// x 256 thr; 4 uint4 (16 elements) per thread, all loads issued up front.
// ============================================================================
__global__ __launch_bounds__(256) void gather_kernel(const uint4* __restrict__ sm4) {
    __shared__ uint32_t scand[8 * WCAP];

    const int t    = threadIdx.x;
    const int lane = t & 31;
    const int w    = t >> 5;
    const int b    = blockIdx.x >> 4;              // 16 blocks per batch
    const int base = blockIdx.x * 1024;            // uint4 base for this block

    const uint32_t P1 = __float_as_uint(P1F);
    const uint32_t P2 = __float_as_uint(P2F);
    const uint32_t W  = P2 - P1;

    uint4 v[4];
    #pragma unroll
    for (int j = 0; j < 4; j++) v[j] = sm4[base + j * 256 + t];

    uint32_t* wbuf = scand + w * WCAP;
    uint32_t cnt2 = 0;     // count of u >= P2 (per thread)
    uint32_t cw   = 0;     // warp candidate count (uniform across warp)

    #pragma unroll
    for (int j = 0; j < 4; j++) {
        #pragma unroll
        for (int c = 0; c < 4; c++) {
            uint32_t u = (c == 0) ? v[j].x : (c == 1) ? v[j].y
                       : (c == 2) ? v[j].z : v[j].w;
            cnt2 += (u >= P2);
            bool isC = (u - P1) < W;               // P1 <= u < P2 (positive floats)
            unsigned m = __ballot_sync(0xFFFFFFFFu, isC);
            if (isC) {
                uint32_t idx = cw + __popc(m & ((1u << lane) - 1u));
                if (idx < WCAP) wbuf[idx] = u;
            }
            cw += __popc(m);
        }
    }

    // warp-reduce cnt2
    #pragma unroll
    for (int off = 16; off > 0; off >>= 1)
        cnt2 += __shfl_down_sync(0xFFFFFFFFu, cnt2, off);

    uint32_t n = (cw > WCAP) ? WCAP : cw;
    uint32_t gbase = 0;
    if (lane == 0) {
        atomicAdd(&g_c2[b], cnt2);
        if (cw > WCAP) g_of[b] = 1u;
        gbase = atomicAdd(&g_nc[b], n);
        if (gbase + n > CANDCAP) g_of[b] = 1u;
    }
    gbase = __shfl_sync(0xFFFFFFFFu, gbase, 0);
    __syncwarp();
    for (uint32_t i = lane; i < n; i += 32)
        if (gbase + i < CANDCAP) g_cand[b * CANDCAP + gbase + i] = wbuf[i];
}

// ============================================================================
// Kernel 2: per-batch exact threshold. Normal path: candidates in [P1, P2)
// -> select on 20-bit keys (u - P1) in 2 rounds of 10 bits.
// Miss fallback: 4x8-bit full radix over smap (never taken at this input).
// ============================================================================
__device__ __forceinline__ uint32_t suffix_excl_512(uint32_t v, uint32_t* wsum) {
    const int t = threadIdx.x, lane = t & 31, w = t >> 5;
    uint32_t s = v;
    #pragma unroll
    for (int off = 1; off < 32; off <<= 1) {
        uint32_t o = __shfl_down_sync(0xFFFFFFFFu, s, off);
        if (lane + off < 32) s += o;
    }
    if (lane == 0) wsum[w] = s;
    __syncthreads();
    if (t < 32) {
        uint32_t x  = (t < 16) ? wsum[t] : 0u;
        uint32_t sx = x;
        #pragma unroll
        for (int off = 1; off < 16; off <<= 1) {
            uint32_t o = __shfl_down_sync(0xFFFFFFFFu, sx, off);
            if (t + off < 16) sx += o;
        }
        if (t < 16) wsum[t] = sx - x;
    }
    __syncthreads();
    return wsum[w] + (s - v);
}

__global__ __launch_bounds__(512) void thresh_kernel(const float* __restrict__ smap) {
    __shared__ uint32_t hist[1024];
    __shared__ uint32_t wsum[32];
    __shared__ uint32_t sBin, sK;

    const int b = blockIdx.x;
    const int t = threadIdx.x;
    const uint32_t P1 = __float_as_uint(P1F);

    const uint32_t nc = g_nc[b];
    const uint32_t c2 = g_c2[b];
    const bool miss = (g_of[b] != 0u) || (c2 >= KSEL) || (c2 + nc < KSEL) || (nc > CANDCAP);

    const uint32_t* __restrict__ cand = g_cand + b * CANDCAP;
    const uint32_t* __restrict__ full =
        reinterpret_cast<const uint32_t*>(smap) + (size_t)b * NTOK;

    if (!miss) {
        uint32_t Kcur = (uint32_t)KSEL - c2;
        uint32_t prefixVal = 0;          // selected high bits of the 20-bit key
        #pragma unroll
        for (int r = 0; r < 2; r++) {
            const int shift = (r == 0) ? 10 : 0;
            for (int i = t; i < 1024; i += 512) hist[i] = 0u;
            __syncthreads();
            for (uint32_t i = t; i < nc; i += 512) {
                uint32_t k = cand[i] - P1;                     // < 2^20
                bool match = (r == 0) || ((k >> 10) == prefixVal);
                if (match) atomicAdd(&hist[(k >> shift) & 1023u], 1u);
            }
            __syncthreads();
            const int base = t * 2;
            uint32_t p = hist[base] + hist[base + 1];
            uint32_t sfx = suffix_excl_512(p, wsum);
            for (int j = 1; j >= 0; j--) {
                uint32_t h = hist[base + j];
                uint32_t s_incl = sfx + h;
                if (sfx < Kcur && s_incl >= Kcur) { sBin = (uint32_t)(base + j); sK = Kcur - sfx; }
                sfx = s_incl;
            }
            __syncthreads();
            prefixVal = (prefixVal << 10) | sBin;
            Kcur = sK;
            __syncthreads();
        }
        if (t == 0) { g_T[b] = P1 + prefixVal; g_req[b] = Kcur; }
    } else {
        uint32_t Kcur = KSEL;
        uint32_t prefixVal = 0;
        for (int r = 0; r < 4; r++) {
            const int shift = 24 - 8 * r;
            for (int i = t; i < 256; i += 512) hist[i] = 0u;
            __syncthreads();
            for (int i = t; i < NTOK; i += 512) {
                uint32_t u = full[i];
                bool match = (r == 0) || ((u >> (shift + 8)) == prefixVal);
                if (match) atomicAdd(&hist[(u >> shift) & 255u], 1u);
            }
            __syncthreads();
            uint32_t p = (t < 256) ? hist[t] : 0u;
            uint32_t sfx = suffix_excl_512(p, wsum);
            if (t < 256) {
                uint32_t s_incl = sfx + p;
                if (sfx < Kcur && s_incl >= Kcur) { sBin = (uint32_t)t; sK = Kcur - sfx; }
            }
            __syncthreads();
            prefixVal = (prefixVal << 8) | sBin;
            Kcur = sK;
            __syncthreads();
        }
        if (t == 0) { g_T[b] = prefixVal; g_req[b] = Kcur; }
    }
}

// ============================================================================
// Kernel 3: loss sweep (67 MB scores+gumbel DRAM + 16 MB smap, L2-hot).
// term = min(c + max(x,0), 100), x = sel ? -d : d, c = ln(1+e^{-|x|}).
// 2048 blocks x 256 thr x 2 groups/thread (R6 config, best measured).
// ============================================================================
__global__ __launch_bounds__(256) void loss_kernel(const float4* __restrict__ zs4,
                                                   const uint4*  __restrict__ sm4,
                                                   const float4* __restrict__ gn4,
                                                   float* __restrict__ out,
                                                   unsigned nblocks) {
    __shared__ double wpart[8];
    const int t    = threadIdx.x;
    const int lane = t & 31;
    const int w    = t >> 5;
    const int b    = blockIdx.x >> 5;               // 32 blocks per batch
    const int blockBase = blockIdx.x * 512;
    const uint32_t T = g_T[b];

    const int g0 = blockBase + t;
    const int g1 = blockBase + 256 + t;

    uint4  u0 = sm4[g0],                u1 = sm4[g1];
    float4 za0 = __ldcs(&zs4[2 * g0]),  zb0 = __ldcs(&zs4[2 * g0 + 1]);
    float4 za1 = __ldcs(&zs4[2 * g1]),  zb1 = __ldcs(&zs4[2 * g1 + 1]);
    float4 ga0 = __ldcs(&gn4[2 * g0]),  gb0 = __ldcs(&gn4[2 * g0 + 1]);
    float4 ga1 = __ldcs(&gn4[2 * g1]),  gb1 = __ldcs(&gn4[2 * g1 + 1]);

    float d[8];
    d[0] = (za0.x + ga0.x) - (za0.y + ga0.y);
    d[1] = (za0.z + ga0.z) - (za0.w + ga0.w);
    d[2] = (zb0.x + gb0.x) - (zb0.y + gb0.y);
    d[3] = (zb0.z + gb0.z) - (zb0.w + gb0.w);
    d[4] = (za1.x + ga1.x) - (za1.y + ga1.y);
    d[5] = (za1.z + ga1.z) - (za1.w + ga1.w);
    d[6] = (zb1.x + gb1.x) - (zb1.y + gb1.y);
    d[7] = (zb1.z + gb1.z) - (zb1.w + gb1.w);

    uint32_t uu[8] = {u0.x, u0.y, u0.z, u0.w, u1.x, u1.y, u1.z, u1.w};

    float facc = 0.0f;
    #pragma unroll
    for (int k = 0; k < 8; k++) {
        bool sel;
        if (uu[k] > T)       sel = true;
        else if (uu[k] == T) sel = (atomicAdd(&g_eqcnt[b], 1u) < g_req[b]);  // rare
        else                 sel = false;
        float x = sel ? -d[k] : d[k];
        float c = __logf(1.0f + __expf(-fabsf(x)));
        facc += fminf(c + fmaxf(x, 0.0f), 100.0f);
    }

    double acc = (double)facc;
    #pragma unroll
    for (int off = 16; off > 0; off >>= 1)
        acc += __shfl_down_sync(0xFFFFFFFFu, acc, off);
    if (lane == 0) wpart[w] = acc;
    __syncthreads();

    if (t == 0) {
        double bsum = 0.0;
        #pragma unroll
        for (int i = 0; i < 8; i++) bsum += wpart[i];
        atomicAdd(&g_acc, bsum);
        __threadfence();
        unsigned ticket = atomicAdd(&g_done, 1u);
        if (ticket == nblocks - 1) {                 // last block: finalize + reset
            __threadfence();
            out[0] = (float)atomicAdd(&g_acc, 0.0);
            #pragma unroll 4
            for (int i = 0; i < BATCH; i++) {
                g_c2[i] = 0u; g_nc[i] = 0u; g_of[i] = 0u; g_eqcnt[i] = 0u;
            }
            g_acc = 0.0;
            __threadfence();
            g_done = 0u;
        }
    }
}

extern "C" void kernel_launch(void* const* d_in, const int* in_sizes, int n_in,
                              void* d_out, int out_size) {
    const float* scores = (const float*)d_in[0];   // [B, N, 2]
    const float* smap   = (const float*)d_in[1];   // [B, 1, H, W] == [B, N]
    const float* gumb   = (const float*)d_in[2];   // [B, N, 2]
    float* out = (float*)d_out;

    gather_kernel<<<1024, 256>>>((const uint4*)smap);
    thresh_kernel<<<BATCH, 512>>>(smap);
    loss_kernel<<<2048, 256>>>((const float4*)scores, (const uint4*)smap,
                               (const float4*)gumb, out, 2048u);
}

// round 9
// speedup vs baseline: 1.0812x; 1.0728x over previous
#include <cuda_runtime.h>
#include <cstdint>

#define BATCH 64
#define NTOK  65536            // 256*256
#define KSEL  16384
#define TOTAL (BATCH * NTOK)
#define CANDCAP 4096           // per-batch candidate capacity (global)
#define WCAP    64             // per-warp candidate capacity (expected ~20.5, +10 sigma)

// ---- device scratch (device globals; no allocations) ----
__device__ uint2    g_cand[BATCH * CANDCAP];  // (u bits, delta bits)
__device__ uint32_t g_nc[BATCH];     // candidate counts (zero-init; reset by finalize)
__device__ uint32_t g_c2[BATCH];     // counts >= P2     (zero-init; reset by finalize)
__device__ uint32_t g_of[BATCH];     // overflow flags   (zero-init; reset by finalize)
__device__ uint32_t g_eqcnt[BATCH];  // runtime tie counter
__device__ double   g_acc;           // loss accumulator
__device__ unsigned g_done;          // finalize ticket

#define P1F 0.73f
#define P2F 0.77f

// ============================================================================
// Kernel 1: THE sweep (83 MB). Per token:
//   d = (z0+g0)-(z1+g1); sp = c + max(d,0), c = ln(1+e^{-|d|})
//   provisional sel guess: u >= P2 (certain outside window [P1,P2))
//   accumulate min(sp - sel*d, 100); window tokens stash (u, delta) where
//   delta = min(sp-d,100) - min(sp,100)  (applied later if truly selected).
// 2048 blocks x 256 thr x 2 groups/thread (R6-best loss structure).
// ============================================================================
__global__ __launch_bounds__(256) void sweep_kernel(const float4* __restrict__ zs4,
                                                    const uint4*  __restrict__ sm4,
                                                    const float4* __restrict__ gn4) {
    __shared__ uint2    wbuf[8 * WCAP];
    __shared__ uint32_t wcnt[8];
    __shared__ double   wpart[8];
    __shared__ uint32_t wc2[8];

    const int t    = threadIdx.x;
    const int lane = t & 31;
    const int w    = t >> 5;
    const int b    = blockIdx.x >> 5;               // 32 blocks per batch
    const int blockBase = blockIdx.x * 512;

    if (lane == 0) wcnt[w] = 0u;
    __syncwarp();

    const uint32_t P1 = __float_as_uint(P1F);
    const uint32_t P2 = __float_as_uint(P2F);
    const uint32_t W  = P2 - P1;

    const int g0 = blockBase + t;
    const int g1 = blockBase + 256 + t;

    uint4  u0 = sm4[g0],                u1 = sm4[g1];
    float4 za0 = __ldcs(&zs4[2 * g0]),  zb0 = __ldcs(&zs4[2 * g0 + 1]);
    float4 za1 = __ldcs(&zs4[2 * g1]),  zb1 = __ldcs(&zs4[2 * g1 + 1]);
    float4 ga0 = __ldcs(&gn4[2 * g0]),  gb0 = __ldcs(&gn4[2 * g0 + 1]);
    float4 ga1 = __ldcs(&gn4[2 * g1]),  gb1 = __ldcs(&gn4[2 * g1 + 1]);

    float d[8];
    d[0] = (za0.x + ga0.x) - (za0.y + ga0.y);
    d[1] = (za0.z + ga0.z) - (za0.w + ga0.w);
    d[2] = (zb0.x + gb0.x) - (zb0.y + gb0.y);
    d[3] = (zb0.z + gb0.z) - (zb0.w + gb0.w);
    d[4] = (za1.x + ga1.x) - (za1.y + ga1.y);
    d[5] = (za1.z + ga1.z) - (za1.w + ga1.w);
    d[6] = (zb1.x + gb1.x) - (zb1.y + gb1.y);
    d[7] = (zb1.z + gb1.z) - (zb1.w + gb1.w);

    uint32_t uu[8] = {u0.x, u0.y, u0.z, u0.w, u1.x, u1.y, u1.z, u1.w};

    float facc = 0.0f;
    uint32_t cnt2 = 0;
    #pragma unroll
    for (int k = 0; k < 8; k++) {
        const float dd = d[k];
        const uint32_t u = uu[k];
        const float c  = __logf(1.0f + __expf(-fabsf(dd)));
        const float sp = c + fmaxf(dd, 0.0f);
        const float t_un = fminf(sp, 100.0f);
        const float t_se = fminf(sp - dd, 100.0f);
        const bool hi = (u >= P2);
        cnt2 += hi;
        facc += hi ? t_se : t_un;
        if ((u - P1) < W) {                         // rare (~4%): stash correction
            uint32_t idx = atomicAdd(&wcnt[w], 1u);
            if (idx < WCAP) wbuf[w * WCAP + idx] = make_uint2(u, __float_as_uint(t_se - t_un));
        }
    }

    // per-warp reductions
    double acc = (double)facc;
    #pragma unroll
    for (int off = 16; off > 0; off >>= 1) {
        acc  += __shfl_down_sync(0xFFFFFFFFu, acc,  off);
        cnt2 += __shfl_down_sync(0xFFFFFFFFu, cnt2, off);
    }
    if (lane == 0) { wpart[w] = acc; wc2[w] = cnt2; }
    __syncwarp();

    // per-warp candidate flush (independent of other warps)
    uint32_t cw = wcnt[w];
    uint32_t n  = (cw > WCAP) ? WCAP : cw;
    uint32_t gbase = 0;
    if (lane == 0) {
        if (cw > WCAP) g_of[b] = 1u;
        gbase = atomicAdd(&g_nc[b], n);
        if (gbase + n > CANDCAP) g_of[b] = 1u;
    }
    gbase = __shfl_sync(0xFFFFFFFFu, gbase, 0);
    for (uint32_t i = lane; i < n; i += 32)
        if (gbase + i < CANDCAP) g_cand[b * CANDCAP + gbase + i] = wbuf[w * WCAP + i];

    __syncthreads();
    if (t == 0) {
        double bsum = 0.0; uint32_t tot2 = 0;
        #pragma unroll
        for (int i = 0; i < 8; i++) { bsum += wpart[i]; tot2 += wc2[i]; }
        atomicAdd(&g_acc, bsum);
        atomicAdd(&g_c2[b], tot2);
    }
}

// ============================================================================
// Kernel 2: per-batch correction. Normal: 2x10-bit radix select of T among
// candidates (keys u-P1 < 2^20), then sum deltas for u > T (+req ties).
// Miss fallback (never taken): full radix for T over smap + full re-read
// of this batch's data to fix the provisional guess. Finalize via ticket.
// ============================================================================
__device__ __forceinline__ uint32_t suffix_excl_512(uint32_t v, uint32_t* wsum) {
    const int t = threadIdx.x, lane = t & 31, w = t >> 5;
    uint32_t s = v;
    #pragma unroll
    for (int off = 1; off < 32; off <<= 1) {
        uint32_t o = __shfl_down_sync(0xFFFFFFFFu, s, off);
        if (lane + off < 32) s += o;
    }
    if (lane == 0) wsum[w] = s;
    __syncthreads();
    if (t < 32) {
        uint32_t x  = (t < 16) ? wsum[t] : 0u;
        uint32_t sx = x;
        #pragma unroll
        for (int off = 1; off < 16; off <<= 1) {
            uint32_t o = __shfl_down_sync(0xFFFFFFFFu, sx, off);
            if (t + off < 16) sx += o;
        }
        if (t < 16) wsum[t] = sx - x;
    }
    __syncthreads();
    return wsum[w] + (s - v);
}

__global__ __launch_bounds__(512) void fix_kernel(const float4* __restrict__ zs4,
                                                  const float*  __restrict__ smap,
                                                  const float4* __restrict__ gn4,
                                                  float* __restrict__ out) {
    __shared__ uint32_t hist[1024];
    __shared__ uint32_t wsum[32];
    __shared__ uint32_t sBin, sK;
    __shared__ double   dpart[16];

    const int b = blockIdx.x;
    const int t = threadIdx.x;
    const int lane = t & 31;
    const int w    = t >> 5;
    const uint32_t P1 = __float_as_uint(P1F);
    const uint32_t P2 = __float_as_uint(P2F);

    const uint32_t nc = g_nc[b];
    const uint32_t c2 = g_c2[b];
    const bool miss = (g_of[b] != 0u) || (c2 >= KSEL) || (c2 + nc < KSEL) || (nc > CANDCAP);

    const uint2* __restrict__ cand = g_cand + b * CANDCAP;
    const uint32_t* __restrict__ full =
        reinterpret_cast<const uint32_t*>(smap) + (size_t)b * NTOK;

    double corr = 0.0;
    uint32_t T, req;

    if (!miss) {
        // ---- 2-round radix select on 20-bit keys among candidates ----
        uint32_t Kcur = (uint32_t)KSEL - c2;
        uint32_t prefixVal = 0;
        #pragma unroll
        for (int r = 0; r < 2; r++) {
            const int shift = (r == 0) ? 10 : 0;
            for (int i = t; i < 1024; i += 512) hist[i] = 0u;
            __syncthreads();
            for (uint32_t i = t; i < nc; i += 512) {
                uint32_t k = cand[i].x - P1;
                bool match = (r == 0) || ((k >> 10) == prefixVal);
                if (match) atomicAdd(&hist[(k >> shift) & 1023u], 1u);
            }
            __syncthreads();
            const int base = t * 2;
            uint32_t p = hist[base] + hist[base + 1];
            uint32_t sfx = suffix_excl_512(p, wsum);
            for (int j = 1; j >= 0; j--) {
                uint32_t h = hist[base + j];
                uint32_t s_incl = sfx + h;
                if (sfx < Kcur && s_incl >= Kcur) { sBin = (uint32_t)(base + j); sK = Kcur - sfx; }
                sfx = s_incl;
            }
            __syncthreads();
            prefixVal = (prefixVal << 10) | sBin;
            Kcur = sK;
            __syncthreads();
        }
        T = P1 + prefixVal;
        req = sK;

        // ---- sum deltas of truly-selected window tokens ----
        for (uint32_t i = t; i < nc; i += 512) {
            uint2 cv = cand[i];
            if (cv.x > T) corr += (double)__uint_as_float(cv.y);
            else if (cv.x == T) {
                if (atomicAdd(&g_eqcnt[b], 1u) < req)       // rare ties
                    corr += (double)__uint_as_float(cv.y);
            }
        }
    } else {
        // ---- fallback: full 4x8-bit radix for T over this batch's smap ----
        uint32_t Kcur = KSEL;
        uint32_t prefixVal = 0;
        for (int r = 0; r < 4; r++) {
            const int shift = 24 - 8 * r;
            for (int i = t; i < 256; i += 512) hist[i] = 0u;
            __syncthreads();
            for (int i = t; i < NTOK; i += 512) {
                uint32_t u = full[i];
                bool match = (r == 0) || ((u >> (shift + 8)) == prefixVal);
                if (match) atomicAdd(&hist[(u >> shift) & 255u], 1u);
            }
            __syncthreads();
            uint32_t p = (t < 256) ? hist[t] : 0u;
            uint32_t sfx = suffix_excl_512(p, wsum);
            if (t < 256) {
                uint32_t s_incl = sfx + p;
                if (sfx < Kcur && s_incl >= Kcur) { sBin = (uint32_t)t; sK = Kcur - sfx; }
            }
            __syncthreads();
            prefixVal = (prefixVal << 8) | sBin;
            Kcur = sK;
            __syncthreads();
        }
        T = prefixVal;
        req = sK;

        // ---- full correction: re-derive every token's term vs the guess ----
        const float4* zsb = zs4 + (size_t)b * (NTOK / 2);
        const float4* gnb = gn4 + (size_t)b * (NTOK / 2);
        for (int i = t; i < NTOK / 2; i += 512) {       // 2 tokens per float4
            float4 z = zsb[i], g = gnb[i];
            float dv[2] = {(z.x + g.x) - (z.y + g.y), (z.z + g.z) - (z.w + g.w)};
            #pragma unroll
            for (int c = 0; c < 2; c++) {
                uint32_t u = full[2 * i + c];
                bool assumed = (u >= P2);
                bool truesel;
                if (u > T)       truesel = true;
                else if (u == T) truesel = (atomicAdd(&g_eqcnt[b], 1u) < req);
                else             truesel = false;
                if (truesel != assumed) {
                    float dd = dv[c];
                    float cc = __logf(1.0f + __expf(-fabsf(dd)));
                    float sp = cc + fmaxf(dd, 0.0f);
                    float delta = fminf(sp - dd, 100.0f) - fminf(sp, 100.0f);
                    corr += truesel ? (double)delta : -(double)delta;
                }
            }
        }
    }

    // block reduce corr, add to g_acc, finalize via ticket over BATCH blocks
    #pragma unroll
    for (int off = 16; off > 0; off >>= 1)
        corr += __shfl_down_sync(0xFFFFFFFFu, corr, off);
    if (lane == 0) dpart[w] = corr;
    __syncthreads();

    if (t == 0) {
        double bsum = 0.0;
        #pragma unroll
        for (int i = 0; i < 16; i++) bsum += dpart[i];
        atomicAdd(&g_acc, bsum);
        __threadfence();
        unsigned ticket = atomicAdd(&g_done, 1u);
        if (ticket == BATCH - 1) {                   // last block: finalize + reset
            __threadfence();
            out[0] = (float)atomicAdd(&g_acc, 0.0);
            #pragma unroll 4
            for (int i = 0; i < BATCH; i++) {
                g_c2[i] = 0u; g_nc[i] = 0u; g_of[i] = 0u; g_eqcnt[i] = 0u;
            }
            g_acc = 0.0;
            __threadfence();
            g_done = 0u;
        }
    }
}

extern "C" void kernel_launch(void* const* d_in, const int* in_sizes, int n_in,
                              void* d_out, int out_size) {
    const float* scores = (const float*)d_in[0];   // [B, N, 2]
    const float* smap   = (const float*)d_in[1];   // [B, 1, H, W] == [B, N]
    const float* gumb   = (const float*)d_in[2];   // [B, N, 2]
    float* out = (float*)d_out;

    sweep_kernel<<<2048, 256>>>((const float4*)scores, (const uint4*)smap,
                                (const float4*)gumb);
    fix_kernel<<<BATCH, 512>>>((const float4*)scores, smap, (const float4*)gumb, out);
}

// round 10
// speedup vs baseline: 1.1293x; 1.0446x over previous
#include <cuda_runtime.h>
#include <cstdint>

#define BATCH 64
#define NTOK  65536            // 256*256
#define KSEL  16384
#define TOTAL (BATCH * NTOK)
#define CANDCAP 4096           // per-batch candidate capacity (global)
#define WCAP    64             // per-warp candidate capacity (expected ~20.5, +10 sigma)
#define MCAP    64             // boundary-bin member capacity (expected ~3)

// ---- device scratch (device globals; no allocations) ----
__device__ uint2    g_cand[BATCH * CANDCAP];  // (u bits, delta bits)
__device__ uint32_t g_nc[BATCH];     // candidate counts (zero-init; reset by finalize)
__device__ uint32_t g_c2[BATCH];     // counts >= P2     (zero-init; reset by finalize)
__device__ uint32_t g_of[BATCH];     // overflow flags   (zero-init; reset by finalize)
__device__ uint32_t g_eqcnt[BATCH];  // tie counter (fallback only; reset by finalize)
__device__ double   g_acc;           // loss accumulator
__device__ unsigned g_done;          // finalize ticket

#define P1F 0.73f
#define P2F 0.77f

// ============================================================================
// Kernel 1: THE sweep (83 MB). Per token:
//   d = (z0+g0)-(z1+g1); sp = c + max(d,0), c = ln(1+e^{-|d|})
//   provisional sel guess: u >= P2 (certain outside window [P1,P2))
//   accumulate min(sp - sel*d, 100); window tokens stash (u, delta) where
//   delta = min(sp-d,100) - min(sp,100)  (applied later if truly selected).
// ============================================================================
__global__ __launch_bounds__(256) void sweep_kernel(const float4* __restrict__ zs4,
                                                    const uint4*  __restrict__ sm4,
                                                    const float4* __restrict__ gn4) {
    __shared__ uint2    wbuf[8 * WCAP];
    __shared__ uint32_t wcnt[8];
    __shared__ double   wpart[8];
    __shared__ uint32_t wc2[8];

    const int t    = threadIdx.x;
    const int lane = t & 31;
    const int w    = t >> 5;
    const int b    = blockIdx.x >> 5;               // 32 blocks per batch
    const int blockBase = blockIdx.x * 512;

    if (lane == 0) wcnt[w] = 0u;
    __syncwarp();

    const uint32_t P1 = __float_as_uint(P1F);
    const uint32_t P2 = __float_as_uint(P2F);
    const uint32_t W  = P2 - P1;

    const int g0 = blockBase + t;
    const int g1 = blockBase + 256 + t;

    uint4  u0 = sm4[g0],                u1 = sm4[g1];
    float4 za0 = __ldcs(&zs4[2 * g0]),  zb0 = __ldcs(&zs4[2 * g0 + 1]);
    float4 za1 = __ldcs(&zs4[2 * g1]),  zb1 = __ldcs(&zs4[2 * g1 + 1]);
    float4 ga0 = __ldcs(&gn4[2 * g0]),  gb0 = __ldcs(&gn4[2 * g0 + 1]);
    float4 ga1 = __ldcs(&gn4[2 * g1]),  gb1 = __ldcs(&gn4[2 * g1 + 1]);

    float d[8];
    d[0] = (za0.x + ga0.x) - (za0.y + ga0.y);
    d[1] = (za0.z + ga0.z) - (za0.w + ga0.w);
    d[2] = (zb0.x + gb0.x) - (zb0.y + gb0.y);
    d[3] = (zb0.z + gb0.z) - (zb0.w + gb0.w);
    d[4] = (za1.x + ga1.x) - (za1.y + ga1.y);
    d[5] = (za1.z + ga1.z) - (za1.w + ga1.w);
    d[6] = (zb1.x + gb1.x) - (zb1.y + gb1.y);
    d[7] = (zb1.z + gb1.z) - (zb1.w + gb1.w);

    uint32_t uu[8] = {u0.x, u0.y, u0.z, u0.w, u1.x, u1.y, u1.z, u1.w};

    float facc = 0.0f;
    uint32_t cnt2 = 0;
    #pragma unroll
    for (int k = 0; k < 8; k++) {
        const float dd = d[k];
        const uint32_t u = uu[k];
        const float c  = __logf(1.0f + __expf(-fabsf(dd)));
        const float sp = c + fmaxf(dd, 0.0f);
        const float t_un = fminf(sp, 100.0f);
        const float t_se = fminf(sp - dd, 100.0f);
        const bool hi = (u >= P2);
        cnt2 += hi;
        facc += hi ? t_se : t_un;
        if ((u - P1) < W) {                         // rare (~4%): stash correction
            uint32_t idx = atomicAdd(&wcnt[w], 1u);
            if (idx < WCAP) wbuf[w * WCAP + idx] = make_uint2(u, __float_as_uint(t_se - t_un));
        }
    }

    double acc = (double)facc;
    #pragma unroll
    for (int off = 16; off > 0; off >>= 1) {
        acc  += __shfl_down_sync(0xFFFFFFFFu, acc,  off);
        cnt2 += __shfl_down_sync(0xFFFFFFFFu, cnt2, off);
    }
    if (lane == 0) { wpart[w] = acc; wc2[w] = cnt2; }
    __syncwarp();

    uint32_t cw = wcnt[w];
    uint32_t n  = (cw > WCAP) ? WCAP : cw;
    uint32_t gbase = 0;
    if (lane == 0) {
        if (cw > WCAP) g_of[b] = 1u;
        gbase = atomicAdd(&g_nc[b], n);
        if (gbase + n > CANDCAP) g_of[b] = 1u;
    }
    gbase = __shfl_sync(0xFFFFFFFFu, gbase, 0);
    for (uint32_t i = lane; i < n; i += 32)
        if (gbase + i < CANDCAP) g_cand[b * CANDCAP + gbase + i] = wbuf[w * WCAP + i];

    __syncthreads();
    if (t == 0) {
        double bsum = 0.0; uint32_t tot2 = 0;
        #pragma unroll
        for (int i = 0; i < 8; i++) { bsum += wpart[i]; tot2 += wc2[i]; }
        atomicAdd(&g_acc, bsum);
        atomicAdd(&g_c2[b], tot2);
    }
}

// ============================================================================
// Kernel 2: per-batch correction. Normal path (one smem-staged pass):
//   histogram of 1024 bins (key = (u-P1)>>10): count + delta-sum;
//   suffix scan -> boundary bin; corr_hi = sum of delta-sums above it;
//   boundary members (~3) resolved by warp-0 rank select.
// Miss fallback (never taken): full radix + full re-read. Finalize via ticket.
// ============================================================================
__device__ __forceinline__ uint32_t suffix_excl_512(uint32_t v, uint32_t* wsum) {
    const int t = threadIdx.x, lane = t & 31, w = t >> 5;
    uint32_t s = v;
    #pragma unroll
    for (int off = 1; off < 32; off <<= 1) {
        uint32_t o = __shfl_down_sync(0xFFFFFFFFu, s, off);
        if (lane + off < 32) s += o;
    }
    if (lane == 0) wsum[w] = s;
    __syncthreads();
    if (t < 32) {
        uint32_t x  = (t < 16) ? wsum[t] : 0u;
        uint32_t sx = x;
        #pragma unroll
        for (int off = 1; off < 16; off <<= 1) {
            uint32_t o = __shfl_down_sync(0xFFFFFFFFu, sx, off);
            if (t + off < 16) sx += o;
        }
        if (t < 16) wsum[t] = sx - x;
    }
    __syncthreads();
    return wsum[w] + (s - v);
}

__global__ __launch_bounds__(512) void fix_kernel(const float4* __restrict__ zs4,
                                                  const float*  __restrict__ smap,
                                                  const float4* __restrict__ gn4,
                                                  float* __restrict__ out) {
    __shared__ uint2    scand[CANDCAP];     // 32 KB candidate stage
    __shared__ uint32_t hcnt[1024];
    __shared__ float    hsum[1024];
    __shared__ uint32_t wsum[32];
    __shared__ uint32_t sBin, sK, mcnt;
    __shared__ uint32_t mu[MCAP];
    __shared__ float    md[MCAP];
    __shared__ double   dpart[16];

    const int b = blockIdx.x;
    const int t = threadIdx.x;
    const int lane = t & 31;
    const int w    = t >> 5;
    const uint32_t P1 = __float_as_uint(P1F);
    const uint32_t P2 = __float_as_uint(P2F);

    const uint32_t nc = g_nc[b];
    const uint32_t c2 = g_c2[b];
    bool miss = (g_of[b] != 0u) || (c2 >= KSEL) || (c2 + nc < KSEL) || (nc > CANDCAP);

    const uint2* __restrict__ candg = g_cand + b * CANDCAP;
    const uint32_t* __restrict__ full =
        reinterpret_cast<const uint32_t*>(smap) + (size_t)b * NTOK;

    double corr = 0.0;

    if (!miss) {
        // ---- stage candidates + zero histograms (independent loads, high MLP)
        for (uint32_t i = t; i < nc; i += 512) scand[i] = candg[i];
        for (int i = t; i < 1024; i += 512) { hcnt[i] = 0u; hsum[i] = 0.0f; }
        if (t == 0) mcnt = 0u;
        __syncthreads();

        // ---- single histogram pass: count + delta-sum per 10-bit bin
        for (uint32_t i = t; i < nc; i += 512) {
            uint2 cv = scand[i];
            uint32_t bin = (cv.x - P1) >> 10;       // < 1024
            atomicAdd(&hcnt[bin], 1u);
            atomicAdd(&hsum[bin], __uint_as_float(cv.y));
        }
        __syncthreads();

        // ---- suffix scan to locate boundary bin (rank Kcur from the top)
        const uint32_t Kcur = (uint32_t)KSEL - c2;
        const int base = t * 2;
        uint32_t p = hcnt[base] + hcnt[base + 1];
        uint32_t sfx = suffix_excl_512(p, wsum);
        for (int j = 1; j >= 0; j--) {
            uint32_t h = hcnt[base + j];
            uint32_t s_incl = sfx + h;
            if (sfx < Kcur && s_incl >= Kcur) { sBin = (uint32_t)(base + j); sK = Kcur - sfx; }
            sfx = s_incl;
        }
        __syncthreads();
        const uint32_t bin = sBin;
        const uint32_t rk  = sK;            // how many to take from boundary bin

        // ---- corr_hi: delta-sums of bins strictly above boundary
        float ch = 0.0f;
        for (int i = t; i < 1024; i += 512)
            if ((uint32_t)i > bin) ch += hsum[i];
        corr += (double)ch;

        // ---- gather boundary-bin members (expected ~3)
        for (uint32_t i = t; i < nc; i += 512) {
            uint2 cv = scand[i];
            if (((cv.x - P1) >> 10) == bin) {
                uint32_t idx = atomicAdd(&mcnt, 1u);
                if (idx < MCAP) { mu[idx] = cv.x; md[idx] = __uint_as_float(cv.y); }
            }
        }
        __syncthreads();

        if (mcnt <= MCAP) {
            // ---- warp-0 rank select among m members: take top rk (ties by index)
            if (w == 0) {
                const uint32_t m = mcnt;
                float csum = 0.0f;
                for (uint32_t e = lane; e < m; e += 32) {
                    uint32_t ue = mu[e];
                    uint32_t rank = 0;
                    for (uint32_t j = 0; j < m; j++) {
                        uint32_t uj = mu[j];
                        rank += (uj > ue) || (uj == ue && j < e);
                    }
                    if (rank < rk) csum += md[e];
                }
                #pragma unroll
                for (int off = 16; off > 0; off >>= 1)
                    csum += __shfl_down_sync(0xFFFFFFFFu, csum, off);
                if (lane == 0) corr += (double)csum;
            }
        } else {
            miss = true;    // absurdly full boundary bin: use exact fallback
            corr = 0.0;
        }
        __syncthreads();
    }

    if (miss) {
        // ---- fallback: full 4x8-bit radix for T over this batch's smap ----
        uint32_t Kcur = KSEL;
        uint32_t prefixVal = 0;
        for (int r = 0; r < 4; r++) {
            const int shift = 24 - 8 * r;
            for (int i = t; i < 256; i += 512) hcnt[i] = 0u;
            __syncthreads();
            for (int i = t; i < NTOK; i += 512) {
                uint32_t u = full[i];
                bool match = (r == 0) || ((u >> (shift + 8)) == prefixVal);
                if (match) atomicAdd(&hcnt[(u >> shift) & 255u], 1u);
            }
            __syncthreads();
            uint32_t p = (t < 256) ? hcnt[t] : 0u;
            uint32_t sfx = suffix_excl_512(p, wsum);
            if (t < 256) {
                uint32_t s_incl = sfx + p;
                if (sfx < Kcur && s_incl >= Kcur) { sBin = (uint32_t)t; sK = Kcur - sfx; }
            }
            __syncthreads();
            prefixVal = (prefixVal << 8) | sBin;
            Kcur = sK;
            __syncthreads();
        }
        const uint32_t T = prefixVal;
        const uint32_t req = sK;

        // ---- full correction vs the provisional guess ----
        corr = 0.0;
        const float4* zsb = zs4 + (size_t)b * (NTOK / 2);
        const float4* gnb = gn4 + (size_t)b * (NTOK / 2);
        for (int i = t; i < NTOK / 2; i += 512) {       // 2 tokens per float4
            float4 z = zsb[i], g = gnb[i];
            float dv[2] = {(z.x + g.x) - (z.y + g.y), (z.z + g.z) - (z.w + g.w)};
            #pragma unroll
            for (int c = 0; c < 2; c++) {
                uint32_t u = full[2 * i + c];
                bool assumed = (u >= P2);
                bool truesel;
                if (u > T)       truesel = true;
                else if (u == T) truesel = (atomicAdd(&g_eqcnt[b], 1u) < req);
                else             truesel = false;
                if (truesel != assumed) {
                    float dd = dv[c];
                    float cc = __logf(1.0f + __expf(-fabsf(dd)));
                    float sp = cc + fmaxf(dd, 0.0f);
                    float delta = fminf(sp - dd, 100.0f) - fminf(sp, 100.0f);
                    corr += truesel ? (double)delta : -(double)delta;
                }
            }
        }
    }

    // ---- block reduce corr, add, finalize via ticket over BATCH blocks ----
    #pragma unroll
    for (int off = 16; off > 0; off >>= 1)
        corr += __shfl_down_sync(0xFFFFFFFFu, corr, off);
    if (lane == 0) dpart[w] = corr;
    __syncthreads();

    if (t == 0) {
        double bsum = 0.0;
        #pragma unroll
        for (int i = 0; i < 16; i++) bsum += dpart[i];
        atomicAdd(&g_acc, bsum);
        __threadfence();
        unsigned ticket = atomicAdd(&g_done, 1u);
        if (ticket == BATCH - 1) {                   // last block: finalize + reset
            __threadfence();
            out[0] = (float)atomicAdd(&g_acc, 0.0);
            #pragma unroll 4
            for (int i = 0; i < BATCH; i++) {
                g_c2[i] = 0u; g_nc[i] = 0u; g_of[i] = 0u; g_eqcnt[i] = 0u;
            }
            g_acc = 0.0;
            __threadfence();
            g_done = 0u;
        }
    }
}

extern "C" void kernel_launch(void* const* d_in, const int* in_sizes, int n_in,
                              void* d_out, int out_size) {
    const float* scores = (const float*)d_in[0];   // [B, N, 2]
    const float* smap   = (const float*)d_in[1];   // [B, 1, H, W] == [B, N]
    const float* gumb   = (const float*)d_in[2];   // [B, N, 2]
    float* out = (float*)d_out;

    sweep_kernel<<<2048, 256>>>((const float4*)scores, (const uint4*)smap,
                                (const float4*)gumb);
    fix_kernel<<<BATCH, 512>>>((const float4*)scores, smap, (const float4*)gumb, out);
}